// round 1
// baseline (speedup 1.0000x reference)
#include <cuda_runtime.h>

// Direction table: E = 2,000,000 edges; float4 for 16B-aligned single-sector-pair
// gathers. 2.1M * 16B = 33.6 MB static __device__ array (allowed; fits in L2).
#define MAX_E 2100000

static __device__ float4 g_dir[MAX_E];
static __device__ int    g_idx_is64;

// ---------------------------------------------------------------------------
// Detect whether the index arrays are int64 or int32.
// If int64 (little-endian, values < 2M), every odd 32-bit word is zero.
// If int32 (uniform random in [0, 2M)), P(word==0) ~ 5e-7, so ~0 of 256 hit.
// ---------------------------------------------------------------------------
__global__ void detect_idx_kernel(const unsigned int* __restrict__ words, int n_pairs)
{
    if (threadIdx.x != 0 || blockIdx.x != 0) return;
    int n = n_pairs < 256 ? n_pairs : 256;
    int zeros = 0;
    for (int i = 0; i < n; ++i)
        zeros += (words[2 * i + 1] == 0u) ? 1 : 0;
    g_idx_is64 = (zeros >= (n * 3) / 4) ? 1 : 0;
}

// ---------------------------------------------------------------------------
// Pass 1: dir[i] = vec[i] / max(dist[i], 1e-5)
// ---------------------------------------------------------------------------
__global__ void dir_kernel(const float* __restrict__ dist,
                           const float* __restrict__ vec,
                           int E)
{
    int i = blockIdx.x * blockDim.x + threadIdx.x;
    if (i >= E) return;
    float d   = fmaxf(dist[i], 1e-5f);
    float inv = 1.0f / d;
    float x = vec[3 * i + 0] * inv;
    float y = vec[3 * i + 1] * inv;
    float z = vec[3 * i + 2] * inv;
    g_dir[i] = make_float4(x, y, z, 0.0f);
}

// ---------------------------------------------------------------------------
// Pass 2: per angle pair, gather both directions, dot, acos(0.95 * cos)
// ---------------------------------------------------------------------------
__global__ void angle_kernel(const void* __restrict__ src_v,
                             const void* __restrict__ dst_v,
                             float* __restrict__ out,
                             int A)
{
    int i = blockIdx.x * blockDim.x + threadIdx.x;
    if (i >= A) return;

    int s, d;
    if (g_idx_is64) {
        s = (int)((const long long*)src_v)[i];
        d = (int)((const long long*)dst_v)[i];
    } else {
        s = ((const int*)src_v)[i];
        d = ((const int*)dst_v)[i];
    }

    float4 a = __ldg(&g_dir[s]);
    float4 b = __ldg(&g_dir[d]);
    float c = a.x * b.x + a.y * b.y + a.z * b.z;
    out[i] = acosf(0.95f * c);
}

// ---------------------------------------------------------------------------
// Launch
// inputs (metadata order): distances [E] f32, vec [E,3] f32,
//                          angle_src [A] int64/int32, angle_dst [A] int64/int32
// output: angles [A] f32
// ---------------------------------------------------------------------------
extern "C" void kernel_launch(void* const* d_in, const int* in_sizes, int n_in,
                              void* d_out, int out_size)
{
    const float* dist = (const float*)d_in[0];
    const float* vec  = (const float*)d_in[1];
    const void*  src  = d_in[2];
    const void*  dst  = d_in[3];
    float*       out  = (float*)d_out;

    int E = in_sizes[0];
    int A = in_sizes[2];
    if (E > MAX_E) E = MAX_E;  // defensive; reference uses E = 2,000,000

    detect_idx_kernel<<<1, 32>>>((const unsigned int*)src, A);

    const int T = 256;
    dir_kernel<<<(E + T - 1) / T, T>>>(dist, vec, E);
    angle_kernel<<<(A + T - 1) / T, T>>>(src, dst, out, A);
}

// round 7
// speedup vs baseline: 1.0882x; 1.0882x over previous
#include <cuda_runtime.h>

// Direction table: E = 2,000,000 edges; float4 for 16B-aligned gathers.
// 2.1M * 16B = 33.6 MB static __device__ array; fully L2-resident (126 MB L2).
#define MAX_E 2100000

static __device__ float4 g_dir[MAX_E];
static __device__ int    g_idx_is64;

// ---------------------------------------------------------------------------
// Cache-policy load/store helpers
// ---------------------------------------------------------------------------
__device__ __forceinline__ unsigned long long evict_last_policy()
{
    unsigned long long pol;
    asm volatile("createpolicy.fractional.L2::evict_last.b64 %0, 1.0;" : "=l"(pol));
    return pol;
}

__device__ __forceinline__ float4 ldg_table(const float4* p, unsigned long long pol)
{
    float4 v;
    asm volatile("ld.global.nc.L2::cache_hint.v4.f32 {%0,%1,%2,%3}, [%4], %5;"
                 : "=f"(v.x), "=f"(v.y), "=f"(v.z), "=f"(v.w)
                 : "l"(p), "l"(pol));
    return v;
}

__device__ __forceinline__ longlong2 ldcs_ll2(const longlong2* p)
{
    longlong2 v;
    asm volatile("ld.global.cs.v2.s64 {%0,%1}, [%2];"
                 : "=l"(v.x), "=l"(v.y) : "l"(p));
    return v;
}

__device__ __forceinline__ int2 ldcs_i2(const int2* p)
{
    int2 v;
    asm volatile("ld.global.cs.v2.s32 {%0,%1}, [%2];"
                 : "=r"(v.x), "=r"(v.y) : "l"(p));
    return v;
}

__device__ __forceinline__ void stcs_f2(float2* p, float2 v)
{
    asm volatile("st.global.cs.v2.f32 [%0], {%1,%2};"
                 :: "l"(p), "f"(v.x), "f"(v.y) : "memory");
}

// ---------------------------------------------------------------------------
// Detect int64 vs int32 indices (parallel: 1 warp, shfl reduction).
// int64 little-endian with values < 2M -> odd 32-bit words are all zero.
// ---------------------------------------------------------------------------
__global__ void detect_idx_kernel(const unsigned int* __restrict__ words, int n_pairs)
{
    int n = n_pairs < 256 ? n_pairs : 256;
    int lane = threadIdx.x;  // 32 threads
    int zeros = 0;
    for (int j = lane; j < n; j += 32)
        zeros += (words[2 * j + 1] == 0u) ? 1 : 0;
    #pragma unroll
    for (int off = 16; off > 0; off >>= 1)
        zeros += __shfl_down_sync(0xFFFFFFFFu, zeros, off);
    if (lane == 0)
        g_idx_is64 = (zeros >= (n * 3) / 4) ? 1 : 0;
}

// ---------------------------------------------------------------------------
// Pass 1: dir[i] = vec[i] / max(dist[i], 1e-5)
// ---------------------------------------------------------------------------
__global__ void dir_kernel(const float* __restrict__ dist,
                           const float* __restrict__ vec,
                           int E)
{
    int i = blockIdx.x * blockDim.x + threadIdx.x;
    if (i >= E) return;
    float inv = 1.0f / fmaxf(dist[i], 1e-5f);
    float x = vec[3 * i + 0] * inv;
    float y = vec[3 * i + 1] * inv;
    float z = vec[3 * i + 2] * inv;
    g_dir[i] = make_float4(x, y, z, 0.0f);
}

// ---------------------------------------------------------------------------
// Pass 2: 2 angle pairs per thread. Streamed index loads (evict-first),
// evict-last table gathers, streamed output stores.
// ---------------------------------------------------------------------------
__global__ void __launch_bounds__(256) angle_kernel(
        const void* __restrict__ src_v,
        const void* __restrict__ dst_v,
        float* __restrict__ out,
        int A)
{
    int t  = blockIdx.x * blockDim.x + threadIdx.x;
    int i0 = t * 2;
    if (i0 >= A) return;

    unsigned long long pol = evict_last_policy();

    int s0, d0, s1 = 0, d1 = 0;
    bool has2 = (i0 + 1 < A);

    if (g_idx_is64) {
        if (has2) {
            longlong2 s = ldcs_ll2((const longlong2*)((const long long*)src_v + i0));
            longlong2 d = ldcs_ll2((const longlong2*)((const long long*)dst_v + i0));
            s0 = (int)s.x; s1 = (int)s.y;
            d0 = (int)d.x; d1 = (int)d.y;
        } else {
            s0 = (int)((const long long*)src_v)[i0];
            d0 = (int)((const long long*)dst_v)[i0];
        }
    } else {
        if (has2) {
            int2 s = ldcs_i2((const int2*)((const int*)src_v + i0));
            int2 d = ldcs_i2((const int2*)((const int*)dst_v + i0));
            s0 = s.x; s1 = s.y;
            d0 = d.x; d1 = d.y;
        } else {
            s0 = ((const int*)src_v)[i0];
            d0 = ((const int*)dst_v)[i0];
        }
    }

    // Issue all gathers before consuming (max MLP).
    float4 a0 = ldg_table(&g_dir[s0], pol);
    float4 b0 = ldg_table(&g_dir[d0], pol);
    if (has2) {
        float4 a1 = ldg_table(&g_dir[s1], pol);
        float4 b1 = ldg_table(&g_dir[d1], pol);
        float c0 = a0.x * b0.x + a0.y * b0.y + a0.z * b0.z;
        float c1 = a1.x * b1.x + a1.y * b1.y + a1.z * b1.z;
        float2 r = make_float2(acosf(0.95f * c0), acosf(0.95f * c1));
        stcs_f2((float2*)(out + i0), r);
    } else {
        float c0 = a0.x * b0.x + a0.y * b0.y + a0.z * b0.z;
        out[i0] = acosf(0.95f * c0);
    }
}

// ---------------------------------------------------------------------------
// Launch
// inputs (metadata order): distances [E] f32, vec [E,3] f32,
//                          angle_src [A] i64/i32, angle_dst [A] i64/i32
// output: angles [A] f32
// ---------------------------------------------------------------------------
extern "C" void kernel_launch(void* const* d_in, const int* in_sizes, int n_in,
                              void* d_out, int out_size)
{
    const float* dist = (const float*)d_in[0];
    const float* vec  = (const float*)d_in[1];
    const void*  src  = d_in[2];
    const void*  dst  = d_in[3];
    float*       out  = (float*)d_out;

    int E = in_sizes[0];
    int A = in_sizes[2];
    if (E > MAX_E) E = MAX_E;

    detect_idx_kernel<<<1, 32>>>((const unsigned int*)src, A);

    const int T = 256;
    dir_kernel<<<(E + T - 1) / T, T>>>(dist, vec, E);

    int threads_needed = (A + 1) / 2;
    angle_kernel<<<(threads_needed + T - 1) / T, T>>>(src, dst, out, A);
}

// round 8
// speedup vs baseline: 1.1722x; 1.0771x over previous
#include <cuda_runtime.h>

// Direction table: E = 2,000,000 edges; float4 for 16B-aligned gathers.
// 2.1M * 16B = 33.6 MB static __device__ array; fully L2-resident (126 MB L2).
#define MAX_E 2100000

static __device__ float4 g_dir[MAX_E];
static __device__ int    g_idx_is64;

// ---------------------------------------------------------------------------
// Cache-policy load/store helpers
// ---------------------------------------------------------------------------
__device__ __forceinline__ unsigned long long evict_last_policy()
{
    unsigned long long pol;
    asm volatile("createpolicy.fractional.L2::evict_last.b64 %0, 1.0;" : "=l"(pol));
    return pol;
}

__device__ __forceinline__ float4 ldg_table(const float4* p, unsigned long long pol)
{
    float4 v;
    asm volatile("ld.global.nc.L2::cache_hint.v4.f32 {%0,%1,%2,%3}, [%4], %5;"
                 : "=f"(v.x), "=f"(v.y), "=f"(v.z), "=f"(v.w)
                 : "l"(p), "l"(pol));
    return v;
}

__device__ __forceinline__ longlong2 ldcs_ll2(const longlong2* p)
{
    longlong2 v;
    asm volatile("ld.global.cs.v2.s64 {%0,%1}, [%2];"
                 : "=l"(v.x), "=l"(v.y) : "l"(p));
    return v;
}

__device__ __forceinline__ int4 ldcs_i4(const int4* p)
{
    int4 v;
    asm volatile("ld.global.cs.v4.s32 {%0,%1,%2,%3}, [%4];"
                 : "=r"(v.x), "=r"(v.y), "=r"(v.z), "=r"(v.w) : "l"(p));
    return v;
}

__device__ __forceinline__ void stcs_f4(float4* p, float4 v)
{
    asm volatile("st.global.cs.v4.f32 [%0], {%1,%2,%3,%4};"
                 :: "l"(p), "f"(v.x), "f"(v.y), "f"(v.z), "f"(v.w) : "memory");
}

// ---------------------------------------------------------------------------
// Pass 1: dir[i] = vec[i] / max(dist[i], 1e-5).
// Block 0 / warp 0 additionally detects int64-vs-int32 indices:
// int64 little-endian with values < 2M -> odd 32-bit words are all zero.
// ---------------------------------------------------------------------------
__global__ void dir_kernel(const float* __restrict__ dist,
                           const float* __restrict__ vec,
                           const unsigned int* __restrict__ idx_words,
                           int n_pairs,
                           int E)
{
    if (blockIdx.x == 0 && threadIdx.x < 32) {
        int n = n_pairs < 256 ? n_pairs : 256;
        int lane = threadIdx.x;
        int zeros = 0;
        for (int j = lane; j < n; j += 32)
            zeros += (idx_words[2 * j + 1] == 0u) ? 1 : 0;
        #pragma unroll
        for (int off = 16; off > 0; off >>= 1)
            zeros += __shfl_down_sync(0xFFFFFFFFu, zeros, off);
        if (lane == 0)
            g_idx_is64 = (zeros >= (n * 3) / 4) ? 1 : 0;
    }

    int i = blockIdx.x * blockDim.x + threadIdx.x;
    if (i >= E) return;
    float inv = 1.0f / fmaxf(dist[i], 1e-5f);
    float x = vec[3 * i + 0] * inv;
    float y = vec[3 * i + 1] * inv;
    float z = vec[3 * i + 2] * inv;
    g_dir[i] = make_float4(x, y, z, 0.0f);
}

// ---------------------------------------------------------------------------
// Pass 2: 4 angle pairs per thread. Streamed index loads (evict-first),
// evict-last table gathers (8 in flight), streamed vector output stores.
// ---------------------------------------------------------------------------
__global__ void __launch_bounds__(256) angle_kernel(
        const void* __restrict__ src_v,
        const void* __restrict__ dst_v,
        float* __restrict__ out,
        int A)
{
    int t  = blockIdx.x * blockDim.x + threadIdx.x;
    int i0 = t * 4;
    if (i0 >= A) return;

    unsigned long long pol = evict_last_policy();
    const int is64 = g_idx_is64;

    if (i0 + 3 < A) {
        int s[4], d[4];
        if (is64) {
            const long long* sp = (const long long*)src_v + i0;
            const long long* dp = (const long long*)dst_v + i0;
            longlong2 sa = ldcs_ll2((const longlong2*)sp);
            longlong2 sb = ldcs_ll2((const longlong2*)(sp + 2));
            longlong2 da = ldcs_ll2((const longlong2*)dp);
            longlong2 db = ldcs_ll2((const longlong2*)(dp + 2));
            s[0] = (int)sa.x; s[1] = (int)sa.y; s[2] = (int)sb.x; s[3] = (int)sb.y;
            d[0] = (int)da.x; d[1] = (int)da.y; d[2] = (int)db.x; d[3] = (int)db.y;
        } else {
            int4 sa = ldcs_i4((const int4*)((const int*)src_v + i0));
            int4 da = ldcs_i4((const int4*)((const int*)dst_v + i0));
            s[0] = sa.x; s[1] = sa.y; s[2] = sa.z; s[3] = sa.w;
            d[0] = da.x; d[1] = da.y; d[2] = da.z; d[3] = da.w;
        }

        // Issue all 8 gathers before consuming (max MLP).
        float4 a0 = ldg_table(&g_dir[s[0]], pol);
        float4 b0 = ldg_table(&g_dir[d[0]], pol);
        float4 a1 = ldg_table(&g_dir[s[1]], pol);
        float4 b1 = ldg_table(&g_dir[d[1]], pol);
        float4 a2 = ldg_table(&g_dir[s[2]], pol);
        float4 b2 = ldg_table(&g_dir[d[2]], pol);
        float4 a3 = ldg_table(&g_dir[s[3]], pol);
        float4 b3 = ldg_table(&g_dir[d[3]], pol);

        float c0 = a0.x * b0.x + a0.y * b0.y + a0.z * b0.z;
        float c1 = a1.x * b1.x + a1.y * b1.y + a1.z * b1.z;
        float c2 = a2.x * b2.x + a2.y * b2.y + a2.z * b2.z;
        float c3 = a3.x * b3.x + a3.y * b3.y + a3.z * b3.z;

        float4 r = make_float4(acosf(0.95f * c0), acosf(0.95f * c1),
                               acosf(0.95f * c2), acosf(0.95f * c3));
        stcs_f4((float4*)(out + i0), r);
    } else {
        for (int i = i0; i < A; ++i) {
            int si, di;
            if (is64) {
                si = (int)((const long long*)src_v)[i];
                di = (int)((const long long*)dst_v)[i];
            } else {
                si = ((const int*)src_v)[i];
                di = ((const int*)dst_v)[i];
            }
            float4 a = ldg_table(&g_dir[si], pol);
            float4 b = ldg_table(&g_dir[di], pol);
            float c = a.x * b.x + a.y * b.y + a.z * b.z;
            out[i] = acosf(0.95f * c);
        }
    }
}

// ---------------------------------------------------------------------------
// Launch
// inputs (metadata order): distances [E] f32, vec [E,3] f32,
//                          angle_src [A] i64/i32, angle_dst [A] i64/i32
// output: angles [A] f32
// ---------------------------------------------------------------------------
extern "C" void kernel_launch(void* const* d_in, const int* in_sizes, int n_in,
                              void* d_out, int out_size)
{
    const float* dist = (const float*)d_in[0];
    const float* vec  = (const float*)d_in[1];
    const void*  src  = d_in[2];
    const void*  dst  = d_in[3];
    float*       out  = (float*)d_out;

    int E = in_sizes[0];
    int A = in_sizes[2];
    if (E > MAX_E) E = MAX_E;

    const int T = 256;
    dir_kernel<<<(E + T - 1) / T, T>>>(dist, vec, (const unsigned int*)src, A, E);

    int threads_needed = (A + 3) / 4;
    angle_kernel<<<(threads_needed + T - 1) / T, T>>>(src, dst, out, A);
}

// round 9
// speedup vs baseline: 1.1986x; 1.0226x over previous
#include <cuda_runtime.h>

// Direction table: E = 2,000,000 edges; float4 for 16B-aligned gathers.
// 2.1M * 16B = 33.6 MB static __device__ array; fully L2-resident (126 MB L2).
#define MAX_E 2100000

static __device__ float4 g_dir[MAX_E];
static __device__ int    g_idx_is64;

// ---------------------------------------------------------------------------
// Cache-policy load/store helpers
// ---------------------------------------------------------------------------
__device__ __forceinline__ unsigned long long evict_last_policy()
{
    unsigned long long pol;
    asm volatile("createpolicy.fractional.L2::evict_last.b64 %0, 1.0;" : "=l"(pol));
    return pol;
}

__device__ __forceinline__ float4 ldg_table(const float4* p, unsigned long long pol)
{
    float4 v;
    asm volatile("ld.global.nc.L2::cache_hint.v4.f32 {%0,%1,%2,%3}, [%4], %5;"
                 : "=f"(v.x), "=f"(v.y), "=f"(v.z), "=f"(v.w)
                 : "l"(p), "l"(pol));
    return v;
}

__device__ __forceinline__ longlong2 ldcs_ll2(const longlong2* p)
{
    longlong2 v;
    asm volatile("ld.global.cs.v2.s64 {%0,%1}, [%2];"
                 : "=l"(v.x), "=l"(v.y) : "l"(p));
    return v;
}

__device__ __forceinline__ int4 ldcs_i4(const int4* p)
{
    int4 v;
    asm volatile("ld.global.cs.v4.s32 {%0,%1,%2,%3}, [%4];"
                 : "=r"(v.x), "=r"(v.y), "=r"(v.z), "=r"(v.w) : "l"(p));
    return v;
}

__device__ __forceinline__ void stcs_f4(float4* p, float4 v)
{
    asm volatile("st.global.cs.v4.f32 [%0], {%1,%2,%3,%4};"
                 :: "l"(p), "f"(v.x), "f"(v.y), "f"(v.z), "f"(v.w) : "memory");
}

// ---------------------------------------------------------------------------
// Pass 1: dir[i] = vec[i] / max(dist[i], 1e-5).
// Block 0 / warp 0 additionally detects int64-vs-int32 indices:
// int64 little-endian with values < 2M -> odd 32-bit words are all zero.
// ---------------------------------------------------------------------------
__global__ void dir_kernel(const float* __restrict__ dist,
                           const float* __restrict__ vec,
                           const unsigned int* __restrict__ idx_words,
                           int n_pairs,
                           int E)
{
    if (blockIdx.x == 0 && threadIdx.x < 32) {
        int n = n_pairs < 256 ? n_pairs : 256;
        int lane = threadIdx.x;
        int zeros = 0;
        for (int j = lane; j < n; j += 32)
            zeros += (idx_words[2 * j + 1] == 0u) ? 1 : 0;
        #pragma unroll
        for (int off = 16; off > 0; off >>= 1)
            zeros += __shfl_down_sync(0xFFFFFFFFu, zeros, off);
        if (lane == 0)
            g_idx_is64 = (zeros >= (n * 3) / 4) ? 1 : 0;
    }

    int i = blockIdx.x * blockDim.x + threadIdx.x;
    if (i >= E) return;
    float inv = 1.0f / fmaxf(dist[i], 1e-5f);
    float x = vec[3 * i + 0] * inv;
    float y = vec[3 * i + 1] * inv;
    float z = vec[3 * i + 2] * inv;
    g_dir[i] = make_float4(x, y, z, 0.0f);
}

// ---------------------------------------------------------------------------
// Pass 2: 4 angle pairs per thread, gathers in two batches of 4 to keep the
// live register set <= 32 regs (launch_bounds(256,8) -> 100% occupancy).
// Streamed index loads (evict-first), evict-last table gathers, streamed
// vector output stores.
// ---------------------------------------------------------------------------
__global__ void __launch_bounds__(256, 8) angle_kernel(
        const void* __restrict__ src_v,
        const void* __restrict__ dst_v,
        float* __restrict__ out,
        int A)
{
    int t  = blockIdx.x * blockDim.x + threadIdx.x;
    int i0 = t * 4;
    if (i0 >= A) return;

    unsigned long long pol = evict_last_policy();
    const int is64 = g_idx_is64;

    if (i0 + 3 < A) {
        int s[4], d[4];
        if (is64) {
            const long long* sp = (const long long*)src_v + i0;
            const long long* dp = (const long long*)dst_v + i0;
            longlong2 sa = ldcs_ll2((const longlong2*)sp);
            longlong2 sb = ldcs_ll2((const longlong2*)(sp + 2));
            longlong2 da = ldcs_ll2((const longlong2*)dp);
            longlong2 db = ldcs_ll2((const longlong2*)(dp + 2));
            s[0] = (int)sa.x; s[1] = (int)sa.y; s[2] = (int)sb.x; s[3] = (int)sb.y;
            d[0] = (int)da.x; d[1] = (int)da.y; d[2] = (int)db.x; d[3] = (int)db.y;
        } else {
            int4 sa = ldcs_i4((const int4*)((const int*)src_v + i0));
            int4 da = ldcs_i4((const int4*)((const int*)dst_v + i0));
            s[0] = sa.x; s[1] = sa.y; s[2] = sa.z; s[3] = sa.w;
            d[0] = da.x; d[1] = da.y; d[2] = da.z; d[3] = da.w;
        }

        // Batch 1: 4 gathers in flight, consume, release registers.
        float4 a0 = ldg_table(&g_dir[s[0]], pol);
        float4 b0 = ldg_table(&g_dir[d[0]], pol);
        float4 a1 = ldg_table(&g_dir[s[1]], pol);
        float4 b1 = ldg_table(&g_dir[d[1]], pol);
        float c0 = a0.x * b0.x + a0.y * b0.y + a0.z * b0.z;
        float c1 = a1.x * b1.x + a1.y * b1.y + a1.z * b1.z;
        float r0 = acosf(0.95f * c0);
        float r1 = acosf(0.95f * c1);

        // Batch 2.
        float4 a2 = ldg_table(&g_dir[s[2]], pol);
        float4 b2 = ldg_table(&g_dir[d[2]], pol);
        float4 a3 = ldg_table(&g_dir[s[3]], pol);
        float4 b3 = ldg_table(&g_dir[d[3]], pol);
        float c2 = a2.x * b2.x + a2.y * b2.y + a2.z * b2.z;
        float c3 = a3.x * b3.x + a3.y * b3.y + a3.z * b3.z;

        float4 r = make_float4(r0, r1, acosf(0.95f * c2), acosf(0.95f * c3));
        stcs_f4((float4*)(out + i0), r);
    } else {
        for (int i = i0; i < A; ++i) {
            int si, di;
            if (is64) {
                si = (int)((const long long*)src_v)[i];
                di = (int)((const long long*)dst_v)[i];
            } else {
                si = ((const int*)src_v)[i];
                di = ((const int*)dst_v)[i];
            }
            float4 a = ldg_table(&g_dir[si], pol);
            float4 b = ldg_table(&g_dir[di], pol);
            float c = a.x * b.x + a.y * b.y + a.z * b.z;
            out[i] = acosf(0.95f * c);
        }
    }
}

// ---------------------------------------------------------------------------
// Launch
// inputs (metadata order): distances [E] f32, vec [E,3] f32,
//                          angle_src [A] i64/i32, angle_dst [A] i64/i32
// output: angles [A] f32
// ---------------------------------------------------------------------------
extern "C" void kernel_launch(void* const* d_in, const int* in_sizes, int n_in,
                              void* d_out, int out_size)
{
    const float* dist = (const float*)d_in[0];
    const float* vec  = (const float*)d_in[1];
    const void*  src  = d_in[2];
    const void*  dst  = d_in[3];
    float*       out  = (float*)d_out;

    int E = in_sizes[0];
    int A = in_sizes[2];
    if (E > MAX_E) E = MAX_E;

    const int T = 256;
    dir_kernel<<<(E + T - 1) / T, T>>>(dist, vec, (const unsigned int*)src, A, E);

    int threads_needed = (A + 3) / 4;
    angle_kernel<<<(threads_needed + T - 1) / T, T>>>(src, dst, out, A);
}